// round 8
// baseline (speedup 1.0000x reference)
#include <cuda_runtime.h>
#include <cuda_bf16.h>
#include <cstdint>

// ---------------- problem constants ----------------
#define BASE_VOCAB 32000
#define SVG_VOCAB  40000
#define TOTAL_VOCAB 72000
#define EMBED 2048
#define NTOK  2048

#define LM_PAD  72192
#define SVG_PAD 40192
#define HID_ROWS (NTOK + 128)   // pad: svg segment tiles may read past 2048

#define QS        1600.0f       // int8 quant scale (both operands)
#define OUT_SCALE (1.0f / (QS * QS))

// ---------------- scratch (s8) ----------------
__device__ uint8_t g_hidden[(size_t)HID_ROWS * EMBED];
__device__ uint8_t g_lmT[(size_t)LM_PAD * EMBED];
__device__ uint8_t g_svgT[(size_t)SVG_PAD * EMBED];
__device__ int g_perm[NTOK];
__device__ int g_counts[2];

// ---------------- helpers ----------------
__device__ __forceinline__ uint32_t smem_u32(const void* p) {
    uint32_t a;
    asm("{ .reg .u64 t; cvta.to.shared.u64 t, %1; cvt.u32.u64 %0, t; }" : "=r"(a) : "l"(p));
    return a;
}
__device__ __forceinline__ int q8(float x) {
    int v = __float2int_rn(x * QS);
    return max(-127, min(127, v));
}
__device__ __forceinline__ uint32_t pack4_s8(float a, float b, float c, float d) {
    return (uint32_t)(uint8_t)(int8_t)q8(a)
         | ((uint32_t)(uint8_t)(int8_t)q8(b) << 8)
         | ((uint32_t)(uint8_t)(int8_t)q8(c) << 16)
         | ((uint32_t)(uint8_t)(int8_t)q8(d) << 24);
}
__device__ __forceinline__ void cp16(uint32_t dst, const void* src) {
    asm volatile("{ .reg .u64 g; cvta.to.global.u64 g, %1; "
                 "cp.async.cg.shared.global [%0], [g], 16; }"
                 :: "r"(dst), "l"(src) : "memory");
}
#define CP_COMMIT()  asm volatile("cp.async.commit_group;" ::: "memory")
#define CP_WAIT(n)   asm volatile("cp.async.wait_group %0;" :: "n"(n) : "memory")

__device__ __forceinline__ void mma_s8(int* c, const uint32_t* a, const uint32_t* b) {
    asm volatile(
        "mma.sync.aligned.m16n8k32.row.col.s32.s8.s8.s32 "
        "{%0,%1,%2,%3}, {%4,%5,%6,%7}, {%8,%9}, {%0,%1,%2,%3};"
        : "+r"(c[0]), "+r"(c[1]), "+r"(c[2]), "+r"(c[3])
        : "r"(a[0]), "r"(a[1]), "r"(a[2]), "r"(a[3]), "r"(b[0]), "r"(b[1]));
}

// ---------------- small kernels ----------------
__global__ void partition_kernel(const int* __restrict__ ids, const int* __restrict__ sflags) {
    __shared__ int cnt0, s0, s1;
    if (threadIdx.x == 0) { cnt0 = 0; s0 = 0; s1 = 0; }
    __syncthreads();
    for (int t = threadIdx.x; t < NTOK; t += blockDim.x) {
        int id = ids[t];
        bool svg = (sflags[t] == 1) && (id >= BASE_VOCAB) && (id < TOTAL_VOCAB);
        if (!svg) atomicAdd(&cnt0, 1);
    }
    __syncthreads();
    int C0 = cnt0;
    for (int t = threadIdx.x; t < NTOK; t += blockDim.x) {
        int id = ids[t];
        bool svg = (sflags[t] == 1) && (id >= BASE_VOCAB) && (id < TOTAL_VOCAB);
        int slot = svg ? (C0 + atomicAdd(&s1, 1)) : atomicAdd(&s0, 1);
        g_perm[slot] = t;
    }
    __syncthreads();
    if (threadIdx.x == 0) { g_counts[0] = C0; g_counts[1] = NTOK - C0; }
}

__global__ void gather_kernel(const int* __restrict__ ids, const int* __restrict__ sflags,
                              const float* __restrict__ base_embed,
                              const float* __restrict__ svg_embed) {
    int s = blockIdx.x;
    int t = g_perm[s];
    int id = ids[t];
    bool svg = (sflags[t] == 1) && (id >= BASE_VOCAB) && (id < TOTAL_VOCAB);
    const float4* src = (const float4*)(svg ? (svg_embed + (size_t)(id - BASE_VOCAB) * EMBED)
                                            : (base_embed + (size_t)id * EMBED));
    uint32_t* dst = (uint32_t*)(g_hidden + (size_t)s * EMBED);
    for (int i = threadIdx.x; i < EMBED / 4; i += blockDim.x) {
        float4 v = src[i];
        dst[i] = pack4_s8(v.x, v.y, v.z, v.w);
    }
}

// src fp32 [K=2048][V] (V contiguous) -> dst s8 [V][2048] (K contiguous), quantized
__global__ void transpose_kernel(const float* __restrict__ src, uint8_t* __restrict__ dst,
                                 int V) {
    __shared__ float tile[32][33];
    int v0 = blockIdx.x * 32, k0 = blockIdx.y * 32;
    int tx = threadIdx.x, ty = threadIdx.y;  // (32, 8)
#pragma unroll
    for (int i = 0; i < 32; i += 8)
        tile[ty + i][tx] = src[(size_t)(k0 + ty + i) * V + v0 + tx];
    __syncthreads();
    int row = ty * 4 + (tx >> 3);          // 0..31 within tile (V dim)
    int kq  = (tx & 7) * 4;                // 0,4,..,28 within tile (K dim)
    uint32_t* drow = (uint32_t*)(dst + (size_t)(v0 + row) * EMBED + k0 + kq);
    *drow = pack4_s8(tile[row][kq], tile[row][kq + 1], tile[row][kq + 2], tile[row][kq + 3]);
}

__global__ void fillneg_kernel(float* __restrict__ out) {
    int r = blockIdx.x;
    if (r >= g_counts[1]) return;
    int token = g_perm[g_counts[0] + r];
    float4* p = (float4*)(out + (size_t)token * TOTAL_VOCAB);
    float4 v = make_float4(-1e30f, -1e30f, -1e30f, -1e30f);
    for (int i = threadIdx.x; i < BASE_VOCAB / 4; i += blockDim.x) p[i] = v;
}

// ---------------- s8 mma.sync GEMM ----------------
// CTA tile 128(M) x 128(N), K chunk 128 s8 (128 B rows), double-buffered cp.async.
// 8 warps: wm = wid>>1 (4 along M, 32 rows), wn = wid&1 (2 along N, 64 cols).
#define KT   128                // s8 elements per K chunk (128 B rows)
#define MT   128
#define NT   128
#define KCH  (EMBED / KT)       // 16
#define ROWU 36                 // uint32 per smem row: 32 data + 4 pad (16B-aligned)
#define ABU  (MT * ROWU)        // uint32 per A stage: 4608
#define STU  (2 * ABU)          // A + B per stage: 9216 uint32
#define SMEM_BYTES (2 * STU * 4)   // 73728

__global__ void __launch_bounds__(256, 2)
gemm_kernel(const uint8_t* __restrict__ Bmat, float* __restrict__ out,
            int Ncols, int colOff, int sel) {
    int count = g_counts[sel];
    int mt = blockIdx.x, nb = blockIdx.y;
    if (mt * MT >= count) return;
    int segBase = sel ? g_counts[0] : 0;

    extern __shared__ uint32_t sm[];
    uint32_t sm_b = smem_u32(sm);
    int tid = threadIdx.x;
    int wid = tid >> 5, lane = tid & 31;
    int g = lane >> 2, t = lane & 3;
    int wm = wid >> 1, wn = wid & 1;

    const uint8_t* Aptr = g_hidden + (size_t)(segBase + mt * MT) * EMBED;
    const uint8_t* Bptr = Bmat + (size_t)(nb * NT) * EMBED;

    auto load_chunk = [&](int k, int buf) {
        int k0 = k * KT;
        uint32_t sA = sm_b + buf * STU * 4;
        uint32_t sB = sA + ABU * 4;
#pragma unroll
        for (int j = 0; j < 4; j++) {
            int i = tid + j * 256;
            int r = i >> 3, q = i & 7;
            cp16(sA + r * (ROWU * 4) + q * 16, Aptr + (size_t)r * EMBED + k0 + q * 16);
        }
#pragma unroll
        for (int j = 0; j < 4; j++) {
            int i = tid + j * 256;
            int r = i >> 3, q = i & 7;
            cp16(sB + r * (ROWU * 4) + q * 16, Bptr + (size_t)r * EMBED + k0 + q * 16);
        }
        CP_COMMIT();
    };

    int acc[2][8][4];
#pragma unroll
    for (int mf = 0; mf < 2; mf++)
#pragma unroll
        for (int nf = 0; nf < 8; nf++)
#pragma unroll
            for (int i = 0; i < 4; i++) acc[mf][nf][i] = 0;

    load_chunk(0, 0);

#pragma unroll 1
    for (int k = 0; k < KCH; k++) {
        int buf = k & 1;
        if (k + 1 < KCH) { load_chunk(k + 1, (k + 1) & 1); CP_WAIT(1); }
        else             { CP_WAIT(0); }
        __syncthreads();

        const uint32_t* As = sm + buf * STU;
        const uint32_t* Bs = sm + buf * STU + ABU;
#pragma unroll
        for (int ks = 0; ks < 4; ks++) {           // 4 x k32 per chunk
            int kb = ks * 8 + t;                   // uint32 (s8 x4) index in row
            uint32_t a[2][4];
#pragma unroll
            for (int mf = 0; mf < 2; mf++) {
                int r0 = wm * 32 + mf * 16 + g;
                a[mf][0] = As[r0 * ROWU + kb];
                a[mf][1] = As[(r0 + 8) * ROWU + kb];
                a[mf][2] = As[r0 * ROWU + kb + 4];
                a[mf][3] = As[(r0 + 8) * ROWU + kb + 4];
            }
            uint32_t b[8][2];
#pragma unroll
            for (int nf = 0; nf < 8; nf++) {
                int c0 = wn * 64 + nf * 8 + g;
                b[nf][0] = Bs[c0 * ROWU + kb];
                b[nf][1] = Bs[c0 * ROWU + kb + 4];
            }
#pragma unroll
            for (int mf = 0; mf < 2; mf++)
#pragma unroll
                for (int nf = 0; nf < 8; nf++)
                    mma_s8(acc[mf][nf], a[mf], b[nf]);
        }
        __syncthreads();
    }

    // epilogue: scatter rows through the token permutation, undo quant scaling
#pragma unroll
    for (int mf = 0; mf < 2; mf++) {
#pragma unroll
        for (int sub = 0; sub < 2; sub++) {
            int rloc = wm * 32 + mf * 16 + g + sub * 8;
            int grow = mt * MT + rloc;
            if (grow >= count) continue;
            int token = g_perm[segBase + grow];
            float* orow = out + (size_t)token * TOTAL_VOCAB + colOff
                        + (size_t)nb * NT + wn * 64;
#pragma unroll
            for (int nf = 0; nf < 8; nf++) {
                int c = nb * NT + wn * 64 + nf * 8 + 2 * t;
                if (c < Ncols) {
                    float2 v = make_float2((float)acc[mf][nf][2 * sub] * OUT_SCALE,
                                           (float)acc[mf][nf][2 * sub + 1] * OUT_SCALE);
                    *(float2*)(orow + nf * 8 + 2 * t) = v;
                }
            }
        }
    }
}

// ---------------- launch ----------------
extern "C" void kernel_launch(void* const* d_in, const int* in_sizes, int n_in,
                              void* d_out, int out_size) {
    const int*   input_ids  = (const int*)d_in[0];
    const int*   svg_flags  = (const int*)d_in[1];
    const float* base_embed = (const float*)d_in[2];
    const float* svg_embed  = (const float*)d_in[3];
    const float* lm_head    = (const float*)d_in[4];
    const float* svg_proj   = (const float*)d_in[5];
    float* out = (float*)d_out;

    cudaFuncSetAttribute(gemm_kernel, cudaFuncAttributeMaxDynamicSharedMemorySize, SMEM_BYTES);

    uint8_t* lmT;  cudaGetSymbolAddress((void**)&lmT,  g_lmT);
    uint8_t* svgT; cudaGetSymbolAddress((void**)&svgT, g_svgT);

    partition_kernel<<<1, 256>>>(input_ids, svg_flags);
    gather_kernel<<<NTOK, 256>>>(input_ids, svg_flags, base_embed, svg_embed);
    transpose_kernel<<<dim3(TOTAL_VOCAB / 32, EMBED / 32), dim3(32, 8)>>>(lm_head, lmT, TOTAL_VOCAB);
    transpose_kernel<<<dim3(SVG_VOCAB / 32, EMBED / 32), dim3(32, 8)>>>(svg_proj, svgT, SVG_VOCAB);
    fillneg_kernel<<<NTOK, 256>>>(out);

    int lm_nb  = (TOTAL_VOCAB + NT - 1) / NT;   // 563
    int svg_nb = (SVG_VOCAB + NT - 1) / NT;     // 313
    gemm_kernel<<<dim3(16, lm_nb),  256, SMEM_BYTES>>>(lmT,  out, TOTAL_VOCAB, 0, 0);
    gemm_kernel<<<dim3(16, svg_nb), 256, SMEM_BYTES>>>(svgT, out, SVG_VOCAB, BASE_VOCAB, 1);
}

// round 9
// speedup vs baseline: 1.6198x; 1.6198x over previous
#include <cuda_runtime.h>
#include <cuda_bf16.h>
#include <cuda_fp16.h>
#include <cstdint>

// ---------------- problem constants ----------------
#define BASE_VOCAB 32000
#define SVG_VOCAB  40000
#define TOTAL_VOCAB 72000
#define EMBED 2048
#define NTOK  2048

#define LM_PAD  72192
#define SVG_PAD 40192
#define HID_ROWS (NTOK + 128)   // pad: svg segment tiles may read past 2048

#define FP8_SCALE    64.0f      // applied to both operands pre-quantization
#define OUT_SCALE    (1.0f / (FP8_SCALE * FP8_SCALE))

// ---------------- scratch (e4m3) ----------------
__device__ uint8_t g_hidden[(size_t)HID_ROWS * EMBED];
__device__ uint8_t g_lmT[(size_t)LM_PAD * EMBED];
__device__ uint8_t g_svgT[(size_t)SVG_PAD * EMBED];
__device__ int g_perm[NTOK];
__device__ int g_counts[2];

// ---------------- helpers ----------------
__device__ __forceinline__ uint32_t smem_u32(const void* p) {
    uint32_t a;
    asm("{ .reg .u64 t; cvta.to.shared.u64 t, %1; cvt.u32.u64 %0, t; }" : "=r"(a) : "l"(p));
    return a;
}
// pack two floats -> two e4m3 bytes (hi<<8 | lo)
__device__ __forceinline__ uint16_t f2e4m3x2(float hi, float lo) {
    uint16_t v;
    asm("cvt.rn.satfinite.e4m3x2.f32 %0, %1, %2;" : "=h"(v) : "f"(hi), "f"(lo));
    return v;
}
__device__ __forceinline__ uint32_t pack4_e4m3(float a, float b, float c, float d) {
    uint32_t lo = f2e4m3x2(b, a);
    uint32_t hi = f2e4m3x2(d, c);
    return lo | (hi << 16);
}
__device__ __forceinline__ void cp16(uint32_t dst, const void* src) {
    asm volatile("{ .reg .u64 g; cvta.to.global.u64 g, %1; "
                 "cp.async.cg.shared.global [%0], [g], 16; }"
                 :: "r"(dst), "l"(src) : "memory");
}
#define CP_COMMIT()  asm volatile("cp.async.commit_group;" ::: "memory")
#define CP_WAIT(n)   asm volatile("cp.async.wait_group %0;" :: "n"(n) : "memory")

// fp8 e4m3 x e4m3 -> f16 accumulate (2 c-regs). Hypothesis: 2x rate of f32-acc.
__device__ __forceinline__ void mma_fp8_h(uint32_t* c, const uint32_t* a, const uint32_t* b) {
    asm volatile(
        "mma.sync.aligned.m16n8k32.row.col.f16.e4m3.e4m3.f16 "
        "{%0,%1}, {%2,%3,%4,%5}, {%6,%7}, {%0,%1};"
        : "+r"(c[0]), "+r"(c[1])
        : "r"(a[0]), "r"(a[1]), "r"(a[2]), "r"(a[3]), "r"(b[0]), "r"(b[1]));
}

// ---------------- small kernels ----------------
__global__ void partition_kernel(const int* __restrict__ ids, const int* __restrict__ sflags) {
    __shared__ int cnt0, s0, s1;
    if (threadIdx.x == 0) { cnt0 = 0; s0 = 0; s1 = 0; }
    __syncthreads();
    for (int t = threadIdx.x; t < NTOK; t += blockDim.x) {
        int id = ids[t];
        bool svg = (sflags[t] == 1) && (id >= BASE_VOCAB) && (id < TOTAL_VOCAB);
        if (!svg) atomicAdd(&cnt0, 1);
    }
    __syncthreads();
    int C0 = cnt0;
    for (int t = threadIdx.x; t < NTOK; t += blockDim.x) {
        int id = ids[t];
        bool svg = (sflags[t] == 1) && (id >= BASE_VOCAB) && (id < TOTAL_VOCAB);
        int slot = svg ? (C0 + atomicAdd(&s1, 1)) : atomicAdd(&s0, 1);
        g_perm[slot] = t;
    }
    __syncthreads();
    if (threadIdx.x == 0) { g_counts[0] = C0; g_counts[1] = NTOK - C0; }
}

__global__ void gather_kernel(const int* __restrict__ ids, const int* __restrict__ sflags,
                              const float* __restrict__ base_embed,
                              const float* __restrict__ svg_embed) {
    int s = blockIdx.x;
    int t = g_perm[s];
    int id = ids[t];
    bool svg = (sflags[t] == 1) && (id >= BASE_VOCAB) && (id < TOTAL_VOCAB);
    const float4* src = (const float4*)(svg ? (svg_embed + (size_t)(id - BASE_VOCAB) * EMBED)
                                            : (base_embed + (size_t)id * EMBED));
    uint32_t* dst = (uint32_t*)(g_hidden + (size_t)s * EMBED);
    for (int i = threadIdx.x; i < EMBED / 4; i += blockDim.x) {
        float4 v = src[i];
        dst[i] = pack4_e4m3(v.x * FP8_SCALE, v.y * FP8_SCALE, v.z * FP8_SCALE, v.w * FP8_SCALE);
    }
}

// src fp32 [K=2048][V] (V contiguous) -> dst e4m3 [V][2048] (K contiguous), scaled
__global__ void transpose_kernel(const float* __restrict__ src, uint8_t* __restrict__ dst,
                                 int V) {
    __shared__ float tile[32][33];
    int v0 = blockIdx.x * 32, k0 = blockIdx.y * 32;
    int tx = threadIdx.x, ty = threadIdx.y;  // (32, 8)
#pragma unroll
    for (int i = 0; i < 32; i += 8)
        tile[ty + i][tx] = src[(size_t)(k0 + ty + i) * V + v0 + tx];
    __syncthreads();
    int row = ty * 4 + (tx >> 3);          // 0..31 within tile (V dim)
    int kq  = (tx & 7) * 4;                // 0,4,..,28 within tile (K dim)
    uint32_t* drow = (uint32_t*)(dst + (size_t)(v0 + row) * EMBED + k0 + kq);
    *drow = pack4_e4m3(tile[row][kq] * FP8_SCALE, tile[row][kq + 1] * FP8_SCALE,
                       tile[row][kq + 2] * FP8_SCALE, tile[row][kq + 3] * FP8_SCALE);
}

__global__ void fillneg_kernel(float* __restrict__ out) {
    int r = blockIdx.x;
    if (r >= g_counts[1]) return;
    int token = g_perm[g_counts[0] + r];
    float4* p = (float4*)(out + (size_t)token * TOTAL_VOCAB);
    float4 v = make_float4(-1e30f, -1e30f, -1e30f, -1e30f);
    for (int i = threadIdx.x; i < BASE_VOCAB / 4; i += blockDim.x) p[i] = v;
}

// ---------------- fp8 (f16-acc) mma.sync GEMM ----------------
// CTA tile 128(M) x 128(N), K chunk 128 e4m3 (128 B rows), double-buffered cp.async.
// 8 warps: wm = wid>>1 (4 along M, 32 rows), wn = wid&1 (2 along N, 64 cols).
#define KT   128                // e4m3 elements per K chunk (128 B rows)
#define MT   128
#define NT   128
#define KCH  (EMBED / KT)       // 16
#define ROWU 36                 // uint32 per smem row: 32 data + 4 pad (16B-aligned)
#define ABU  (MT * ROWU)        // uint32 per A stage: 4608
#define STU  (2 * ABU)          // A + B per stage: 9216 uint32
#define SMEM_BYTES (2 * STU * 4)   // 73728

__global__ void __launch_bounds__(256, 2)
gemm_kernel(const uint8_t* __restrict__ Bmat, float* __restrict__ out,
            int Ncols, int colOff, int sel) {
    int count = g_counts[sel];
    int mt = blockIdx.x, nb = blockIdx.y;
    if (mt * MT >= count) return;
    int segBase = sel ? g_counts[0] : 0;

    extern __shared__ uint32_t sm[];
    uint32_t sm_b = smem_u32(sm);
    int tid = threadIdx.x;
    int wid = tid >> 5, lane = tid & 31;
    int g = lane >> 2, t = lane & 3;
    int wm = wid >> 1, wn = wid & 1;

    const uint8_t* Aptr = g_hidden + (size_t)(segBase + mt * MT) * EMBED;
    const uint8_t* Bptr = Bmat + (size_t)(nb * NT) * EMBED;

    auto load_chunk = [&](int k, int buf) {
        int k0 = k * KT;
        uint32_t sA = sm_b + buf * STU * 4;
        uint32_t sB = sA + ABU * 4;
#pragma unroll
        for (int j = 0; j < 4; j++) {
            int i = tid + j * 256;
            int r = i >> 3, q = i & 7;
            cp16(sA + r * (ROWU * 4) + q * 16, Aptr + (size_t)r * EMBED + k0 + q * 16);
        }
#pragma unroll
        for (int j = 0; j < 4; j++) {
            int i = tid + j * 256;
            int r = i >> 3, q = i & 7;
            cp16(sB + r * (ROWU * 4) + q * 16, Bptr + (size_t)r * EMBED + k0 + q * 16);
        }
        CP_COMMIT();
    };

    uint32_t acc[2][8][2];   // f16x2 accumulators
#pragma unroll
    for (int mf = 0; mf < 2; mf++)
#pragma unroll
        for (int nf = 0; nf < 8; nf++) { acc[mf][nf][0] = 0u; acc[mf][nf][1] = 0u; }

    load_chunk(0, 0);

#pragma unroll 1
    for (int k = 0; k < KCH; k++) {
        int buf = k & 1;
        if (k + 1 < KCH) { load_chunk(k + 1, (k + 1) & 1); CP_WAIT(1); }
        else             { CP_WAIT(0); }
        __syncthreads();

        const uint32_t* As = sm + buf * STU;
        const uint32_t* Bs = sm + buf * STU + ABU;
#pragma unroll
        for (int ks = 0; ks < 4; ks++) {           // 4 x k32 per chunk
            int kb = ks * 8 + t;                   // uint32 (e4m3 x4) index in row
            uint32_t a[2][4];
#pragma unroll
            for (int mf = 0; mf < 2; mf++) {
                int r0 = wm * 32 + mf * 16 + g;
                a[mf][0] = As[r0 * ROWU + kb];
                a[mf][1] = As[(r0 + 8) * ROWU + kb];
                a[mf][2] = As[r0 * ROWU + kb + 4];
                a[mf][3] = As[(r0 + 8) * ROWU + kb + 4];
            }
            uint32_t b[8][2];
#pragma unroll
            for (int nf = 0; nf < 8; nf++) {
                int c0 = wn * 64 + nf * 8 + g;
                b[nf][0] = Bs[c0 * ROWU + kb];
                b[nf][1] = Bs[c0 * ROWU + kb + 4];
            }
#pragma unroll
            for (int mf = 0; mf < 2; mf++)
#pragma unroll
                for (int nf = 0; nf < 8; nf++)
                    mma_fp8_h(acc[mf][nf], a[mf], b[nf]);
        }
        __syncthreads();
    }

    // epilogue: scatter rows through the token permutation, unpack f16, undo scaling
#pragma unroll
    for (int mf = 0; mf < 2; mf++) {
#pragma unroll
        for (int sub = 0; sub < 2; sub++) {
            int rloc = wm * 32 + mf * 16 + g + sub * 8;
            int grow = mt * MT + rloc;
            if (grow >= count) continue;
            int token = g_perm[segBase + grow];
            float* orow = out + (size_t)token * TOTAL_VOCAB + colOff
                        + (size_t)nb * NT + wn * 64;
#pragma unroll
            for (int nf = 0; nf < 8; nf++) {
                int c = nb * NT + wn * 64 + nf * 8 + 2 * t;
                if (c < Ncols) {
                    __half2 h = *(__half2*)&acc[mf][nf][sub];
                    float2 v = make_float2(__half2float(__low2half(h)) * OUT_SCALE,
                                           __half2float(__high2half(h)) * OUT_SCALE);
                    *(float2*)(orow + nf * 8 + 2 * t) = v;
                }
            }
        }
    }
}

// ---------------- launch ----------------
extern "C" void kernel_launch(void* const* d_in, const int* in_sizes, int n_in,
                              void* d_out, int out_size) {
    const int*   input_ids  = (const int*)d_in[0];
    const int*   svg_flags  = (const int*)d_in[1];
    const float* base_embed = (const float*)d_in[2];
    const float* svg_embed  = (const float*)d_in[3];
    const float* lm_head    = (const float*)d_in[4];
    const float* svg_proj   = (const float*)d_in[5];
    float* out = (float*)d_out;

    cudaFuncSetAttribute(gemm_kernel, cudaFuncAttributeMaxDynamicSharedMemorySize, SMEM_BYTES);

    uint8_t* lmT;  cudaGetSymbolAddress((void**)&lmT,  g_lmT);
    uint8_t* svgT; cudaGetSymbolAddress((void**)&svgT, g_svgT);

    partition_kernel<<<1, 256>>>(input_ids, svg_flags);
    gather_kernel<<<NTOK, 256>>>(input_ids, svg_flags, base_embed, svg_embed);
    transpose_kernel<<<dim3(TOTAL_VOCAB / 32, EMBED / 32), dim3(32, 8)>>>(lm_head, lmT, TOTAL_VOCAB);
    transpose_kernel<<<dim3(SVG_VOCAB / 32, EMBED / 32), dim3(32, 8)>>>(svg_proj, svgT, SVG_VOCAB);
    fillneg_kernel<<<NTOK, 256>>>(out);

    int lm_nb  = (TOTAL_VOCAB + NT - 1) / NT;   // 563
    int svg_nb = (SVG_VOCAB + NT - 1) / NT;     // 313
    gemm_kernel<<<dim3(16, lm_nb),  256, SMEM_BYTES>>>(lmT,  out, TOTAL_VOCAB, 0, 0);
    gemm_kernel<<<dim3(16, svg_nb), 256, SMEM_BYTES>>>(svgT, out, SVG_VOCAB, BASE_VOCAB, 1);
}

// round 10
// speedup vs baseline: 2.3444x; 1.4474x over previous
#include <cuda_runtime.h>
#include <cuda_bf16.h>
#include <cstdint>

// ---------------- problem constants ----------------
#define BASE_VOCAB 32000
#define SVG_VOCAB  40000
#define TOTAL_VOCAB 72000
#define EMBED 2048
#define NTOK  2048

#define LM_PAD  72192
#define SVG_PAD 40192
#define HID_ROWS (NTOK + 128)   // pad: svg segment tiles may read past 2048

#define FP8_SCALE    64.0f      // applied to both operands pre-quantization
#define OUT_SCALE    (1.0f / (FP8_SCALE * FP8_SCALE))

// ---------------- scratch (e4m3) ----------------
__device__ uint8_t g_hidden[(size_t)HID_ROWS * EMBED];
__device__ uint8_t g_lmT[(size_t)LM_PAD * EMBED];
__device__ uint8_t g_svgT[(size_t)SVG_PAD * EMBED];
__device__ int g_perm[NTOK];
__device__ int g_counts[2];

// ---------------- helpers ----------------
__device__ __forceinline__ uint32_t smem_u32(const void* p) {
    uint32_t a;
    asm("{ .reg .u64 t; cvta.to.shared.u64 t, %1; cvt.u32.u64 %0, t; }" : "=r"(a) : "l"(p));
    return a;
}
// pack two floats -> two e4m3 bytes (hi<<8 | lo)
__device__ __forceinline__ uint16_t f2e4m3x2(float hi, float lo) {
    uint16_t v;
    asm("cvt.rn.satfinite.e4m3x2.f32 %0, %1, %2;" : "=h"(v) : "f"(hi), "f"(lo));
    return v;
}
__device__ __forceinline__ uint32_t pack4_e4m3(float a, float b, float c, float d) {
    uint32_t lo = f2e4m3x2(b, a);
    uint32_t hi = f2e4m3x2(d, c);
    return lo | (hi << 16);
}
__device__ __forceinline__ void cp16(uint32_t dst, const void* src) {
    asm volatile("{ .reg .u64 g; cvta.to.global.u64 g, %1; "
                 "cp.async.cg.shared.global [%0], [g], 16; }"
                 :: "r"(dst), "l"(src) : "memory");
}
#define CP_COMMIT()  asm volatile("cp.async.commit_group;" ::: "memory")
#define CP_WAIT(n)   asm volatile("cp.async.wait_group %0;" :: "n"(n) : "memory")

__device__ __forceinline__ void ldsm4(uint32_t* r, uint32_t addr) {
    asm volatile("ldmatrix.sync.aligned.m8n8.x4.shared.b16 {%0,%1,%2,%3}, [%4];"
                 : "=r"(r[0]), "=r"(r[1]), "=r"(r[2]), "=r"(r[3]) : "r"(addr));
}

__device__ __forceinline__ void mma_fp8(float* c, const uint32_t* a, const uint32_t* b) {
    asm volatile(
        "mma.sync.aligned.m16n8k32.row.col.f32.e4m3.e4m3.f32 "
        "{%0,%1,%2,%3}, {%4,%5,%6,%7}, {%8,%9}, {%0,%1,%2,%3};"
        : "+f"(c[0]), "+f"(c[1]), "+f"(c[2]), "+f"(c[3])
        : "r"(a[0]), "r"(a[1]), "r"(a[2]), "r"(a[3]), "r"(b[0]), "r"(b[1]));
}

// ---------------- small kernels ----------------
__global__ void partition_kernel(const int* __restrict__ ids, const int* __restrict__ sflags) {
    __shared__ int cnt0, s0, s1;
    if (threadIdx.x == 0) { cnt0 = 0; s0 = 0; s1 = 0; }
    __syncthreads();
    for (int t = threadIdx.x; t < NTOK; t += blockDim.x) {
        int id = ids[t];
        bool svg = (sflags[t] == 1) && (id >= BASE_VOCAB) && (id < TOTAL_VOCAB);
        if (!svg) atomicAdd(&cnt0, 1);
    }
    __syncthreads();
    int C0 = cnt0;
    for (int t = threadIdx.x; t < NTOK; t += blockDim.x) {
        int id = ids[t];
        bool svg = (sflags[t] == 1) && (id >= BASE_VOCAB) && (id < TOTAL_VOCAB);
        int slot = svg ? (C0 + atomicAdd(&s1, 1)) : atomicAdd(&s0, 1);
        g_perm[slot] = t;
    }
    __syncthreads();
    if (threadIdx.x == 0) { g_counts[0] = C0; g_counts[1] = NTOK - C0; }
}

__global__ void gather_kernel(const int* __restrict__ ids, const int* __restrict__ sflags,
                              const float* __restrict__ base_embed,
                              const float* __restrict__ svg_embed) {
    int s = blockIdx.x;
    int t = g_perm[s];
    int id = ids[t];
    bool svg = (sflags[t] == 1) && (id >= BASE_VOCAB) && (id < TOTAL_VOCAB);
    const float4* src = (const float4*)(svg ? (svg_embed + (size_t)(id - BASE_VOCAB) * EMBED)
                                            : (base_embed + (size_t)id * EMBED));
    uint32_t* dst = (uint32_t*)(g_hidden + (size_t)s * EMBED);
    for (int i = threadIdx.x; i < EMBED / 4; i += blockDim.x) {
        float4 v = src[i];
        dst[i] = pack4_e4m3(v.x * FP8_SCALE, v.y * FP8_SCALE, v.z * FP8_SCALE, v.w * FP8_SCALE);
    }
}

// src fp32 [K=2048][V] (V contiguous) -> dst e4m3 [V][2048] (K contiguous), scaled
__global__ void transpose_kernel(const float* __restrict__ src, uint8_t* __restrict__ dst,
                                 int V) {
    __shared__ float tile[32][33];
    int v0 = blockIdx.x * 32, k0 = blockIdx.y * 32;
    int tx = threadIdx.x, ty = threadIdx.y;  // (32, 8)
#pragma unroll
    for (int i = 0; i < 32; i += 8)
        tile[ty + i][tx] = src[(size_t)(k0 + ty + i) * V + v0 + tx];
    __syncthreads();
    int row = ty * 4 + (tx >> 3);          // 0..31 within tile (V dim)
    int kq  = (tx & 7) * 4;                // 0,4,..,28 within tile (K dim)
    uint32_t* drow = (uint32_t*)(dst + (size_t)(v0 + row) * EMBED + k0 + kq);
    *drow = pack4_e4m3(tile[row][kq] * FP8_SCALE, tile[row][kq + 1] * FP8_SCALE,
                       tile[row][kq + 2] * FP8_SCALE, tile[row][kq + 3] * FP8_SCALE);
}

__global__ void fillneg_kernel(float* __restrict__ out) {
    int r = blockIdx.x;
    if (r >= g_counts[1]) return;
    int token = g_perm[g_counts[0] + r];
    float4* p = (float4*)(out + (size_t)token * TOTAL_VOCAB);
    float4 v = make_float4(-1e30f, -1e30f, -1e30f, -1e30f);
    for (int i = threadIdx.x; i < BASE_VOCAB / 4; i += blockDim.x) p[i] = v;
}

// ---------------- fp8 (f32-acc) mma.sync GEMM with ldmatrix ----------------
// CTA tile 128(M) x 128(N), K chunk 128 e4m3 (128 B rows), double-buffered cp.async.
// 8 warps: wm = wid>>1 (4 along M, 32 rows), wn = wid&1 (2 along N, 64 cols).
#define KT   128                // e4m3 elements per K chunk (128 B rows)
#define MT   128
#define NT   128
#define KCH  (EMBED / KT)       // 16
#define ROWU 36                 // uint32 per smem row: 32 data + 4 pad (16B-aligned)
#define ROWB (ROWU * 4)         // 144 bytes
#define ABU  (MT * ROWU)        // uint32 per A stage: 4608
#define STU  (2 * ABU)          // A + B per stage: 9216 uint32
#define SMEM_BYTES (2 * STU * 4)   // 73728

__global__ void __launch_bounds__(256, 2)
gemm_kernel(const uint8_t* __restrict__ Bmat, float* __restrict__ out,
            int Ncols, int colOff, int sel) {
    int count = g_counts[sel];
    int mt = blockIdx.x, nb = blockIdx.y;
    if (mt * MT >= count) return;
    int segBase = sel ? g_counts[0] : 0;

    extern __shared__ uint32_t sm[];
    uint32_t sm_b = smem_u32(sm);
    int tid = threadIdx.x;
    int wid = tid >> 5, lane = tid & 31;
    int g = lane >> 2, t = lane & 3;
    int wm = wid >> 1, wn = wid & 1;

    // ldmatrix per-lane source rows/bytes (m8n8.x4 canonical distribution)
    int l7  = lane & 7, sel8 = lane >> 3;
    int arow  = l7 + (sel8 & 1) * 8;        // A: m0/m2 rows 0-7, m1/m3 rows 8-15
    int abyte = (sel8 >> 1) * 16;           //    m2/m3 at +16B
    int brow  = l7 + (sel8 >> 1) * 8;       // B: m0/m1 first 8 n-rows, m2/m3 next 8
    int bbyte = (sel8 & 1) * 16;            //    m1/m3 at +16B

    const uint8_t* Aptr = g_hidden + (size_t)(segBase + mt * MT) * EMBED;
    const uint8_t* Bptr = Bmat + (size_t)(nb * NT) * EMBED;

    auto load_chunk = [&](int k, int buf) {
        int k0 = k * KT;
        uint32_t sA = sm_b + buf * STU * 4;
        uint32_t sB = sA + ABU * 4;
#pragma unroll
        for (int j = 0; j < 4; j++) {
            int i = tid + j * 256;
            int r = i >> 3, q = i & 7;
            cp16(sA + r * ROWB + q * 16, Aptr + (size_t)r * EMBED + k0 + q * 16);
        }
#pragma unroll
        for (int j = 0; j < 4; j++) {
            int i = tid + j * 256;
            int r = i >> 3, q = i & 7;
            cp16(sB + r * ROWB + q * 16, Bptr + (size_t)r * EMBED + k0 + q * 16);
        }
        CP_COMMIT();
    };

    float acc[2][8][4];
#pragma unroll
    for (int mf = 0; mf < 2; mf++)
#pragma unroll
        for (int nf = 0; nf < 8; nf++)
#pragma unroll
            for (int i = 0; i < 4; i++) acc[mf][nf][i] = 0.f;

    load_chunk(0, 0);

#pragma unroll 1
    for (int k = 0; k < KCH; k++) {
        int buf = k & 1;
        if (k + 1 < KCH) { load_chunk(k + 1, (k + 1) & 1); CP_WAIT(1); }
        else             { CP_WAIT(0); }
        __syncthreads();

        uint32_t sA = sm_b + buf * STU * 4;
        uint32_t sB = sA + ABU * 4;
        // per-lane ldmatrix base addresses
        uint32_t aAddr0 = sA + (uint32_t)(wm * 32 + arow) * ROWB + abyte;        // mf=0
        uint32_t aAddr1 = aAddr0 + 16 * ROWB;                                     // mf=1
        uint32_t bAddr  = sB + (uint32_t)(wn * 64 + brow) * ROWB + bbyte;

#pragma unroll
        for (int ks = 0; ks < 4; ks++) {           // 4 x k32 per chunk
            uint32_t koff = ks * 32;
            uint32_t a[2][4];
            ldsm4(a[0], aAddr0 + koff);
            ldsm4(a[1], aAddr1 + koff);
            uint32_t b[8][2];
#pragma unroll
            for (int p = 0; p < 4; p++)            // nf pairs (2p, 2p+1)
                ldsm4(&b[2 * p][0], bAddr + (uint32_t)(p * 16) * ROWB + koff);
#pragma unroll
            for (int mf = 0; mf < 2; mf++)
#pragma unroll
                for (int nf = 0; nf < 8; nf++)
                    mma_fp8(acc[mf][nf], a[mf], b[nf]);
        }
        __syncthreads();
    }

    // epilogue: scatter rows through the token permutation, undo fp8 scaling
#pragma unroll
    for (int mf = 0; mf < 2; mf++) {
#pragma unroll
        for (int sub = 0; sub < 2; sub++) {
            int rloc = wm * 32 + mf * 16 + g + sub * 8;
            int grow = mt * MT + rloc;
            if (grow >= count) continue;
            int token = g_perm[segBase + grow];
            float* orow = out + (size_t)token * TOTAL_VOCAB + colOff
                        + (size_t)nb * NT + wn * 64;
#pragma unroll
            for (int nf = 0; nf < 8; nf++) {
                int c = nb * NT + wn * 64 + nf * 8 + 2 * t;
                if (c < Ncols) {
                    float2 v = make_float2(acc[mf][nf][2 * sub] * OUT_SCALE,
                                           acc[mf][nf][2 * sub + 1] * OUT_SCALE);
                    *(float2*)(orow + nf * 8 + 2 * t) = v;
                }
            }
        }
    }
}

// ---------------- launch ----------------
extern "C" void kernel_launch(void* const* d_in, const int* in_sizes, int n_in,
                              void* d_out, int out_size) {
    const int*   input_ids  = (const int*)d_in[0];
    const int*   svg_flags  = (const int*)d_in[1];
    const float* base_embed = (const float*)d_in[2];
    const float* svg_embed  = (const float*)d_in[3];
    const float* lm_head    = (const float*)d_in[4];
    const float* svg_proj   = (const float*)d_in[5];
    float* out = (float*)d_out;

    cudaFuncSetAttribute(gemm_kernel, cudaFuncAttributeMaxDynamicSharedMemorySize, SMEM_BYTES);

    uint8_t* lmT;  cudaGetSymbolAddress((void**)&lmT,  g_lmT);
    uint8_t* svgT; cudaGetSymbolAddress((void**)&svgT, g_svgT);

    partition_kernel<<<1, 256>>>(input_ids, svg_flags);
    gather_kernel<<<NTOK, 256>>>(input_ids, svg_flags, base_embed, svg_embed);
    transpose_kernel<<<dim3(TOTAL_VOCAB / 32, EMBED / 32), dim3(32, 8)>>>(lm_head, lmT, TOTAL_VOCAB);
    transpose_kernel<<<dim3(SVG_VOCAB / 32, EMBED / 32), dim3(32, 8)>>>(svg_proj, svgT, SVG_VOCAB);
    fillneg_kernel<<<NTOK, 256>>>(out);

    int lm_nb  = (TOTAL_VOCAB + NT - 1) / NT;   // 563
    int svg_nb = (SVG_VOCAB + NT - 1) / NT;     // 313
    gemm_kernel<<<dim3(16, lm_nb),  256, SMEM_BYTES>>>(lmT,  out, TOTAL_VOCAB, 0, 0);
    gemm_kernel<<<dim3(16, svg_nb), 256, SMEM_BYTES>>>(svgT, out, SVG_VOCAB, BASE_VOCAB, 1);
}